// round 13
// baseline (speedup 1.0000x reference)
#include <cuda_runtime.h>
#include <math.h>

// FraudDetectionHybrid — autoencoder branch is dead code (recon unused).
// R13: cross-round model says the hidden binder is the MUFU/XU pipe
// (rt=8/SMSP; 28 tanh/thread ~= the observed wall; R9-half-rate-f16x2 and
// R10/R11 pipe-swaps all kept total pipe-cycles constant). Escape: one 2-D
// table lookup replaces 12 of 14 tanhs. Fold layers 2-4 + conv + sampler +
// softmax into G2(h0,h1) on (-1,1)^2 (h = tanh of layer 1). Per sample:
// 2 MUFU + 4 LDS + ~14 FMA. Table 97x97 (delta=1/48, err ~2e-4 calibrated
// from R11's measured 1.13e-4 at 1/40), built ONCE by a tiny kernel with
// ACCURATE tanhf, then cooperatively staged into 37.6KB dynamic smem.

#define TN   97
#define TPAD 9412                       // 97*97=9409 padded to /4
__device__ float g_tab2[TPAD];

__device__ __forceinline__ float tanh_fast(float x) {
    float y;
    asm("tanh.approx.f32 %0, %1;" : "=f"(y) : "f"(x));
    return y;
}

// ---------------- kernel 1: build G2 table (accurate math, tiny) ----------------
__global__ __launch_bounds__(256)
void build_table(const float4* __restrict__ fraud_W,   // [4,2,2] = 4 float4
                 const float4* __restrict__ fraud_b,   // [4,2]   = 2 float4
                 const float4* __restrict__ conv_k,
                 const float4* __restrict__ s_W1,
                 const float4* __restrict__ s_b1,
                 const float4* __restrict__ s_W2,
                 const float2* __restrict__ s_b2)
{
    const int idx = blockIdx.x * blockDim.x + threadIdx.x;
    if (idx >= TN * TN) return;
    const int ix = idx % TN;            // h0 axis
    const int iy = idx / TN;            // h1 axis
    float h0 = (float)ix * (1.0f / 48.0f) - 1.0f;
    float h1 = (float)iy * (1.0f / 48.0f) - 1.0f;

    const float4 w1  = __ldg(fraud_W + 1);
    const float4 w2  = __ldg(fraud_W + 2);
    const float4 w3  = __ldg(fraud_W + 3);
    const float4 fb0 = __ldg(fraud_b + 0);
    const float4 fb1 = __ldg(fraud_b + 1);
    const float4 ck  = __ldg(conv_k);
    const float4 W1a = __ldg(s_W1 + 0);
    const float4 W1b = __ldg(s_W1 + 1);
    const float4 b1  = __ldg(s_b1);
    const float4 W2a = __ldg(s_W2 + 0);
    const float4 W2b = __ldg(s_W2 + 1);
    const float2 b2  = __ldg(s_b2);

    // fraud layers 2..4 (accurate tanh)
    float z0 = fmaf(w1.x, h0, fmaf(w1.y, h1, fb0.z));
    float z1 = fmaf(w1.z, h0, fmaf(w1.w, h1, fb0.w));
    h0 = tanhf(z0); h1 = tanhf(z1);
    z0 = fmaf(w2.x, h0, fmaf(w2.y, h1, fb1.x));
    z1 = fmaf(w2.z, h0, fmaf(w2.w, h1, fb1.y));
    h0 = tanhf(z0); h1 = tanhf(z1);
    z0 = fmaf(w3.x, h0, fmaf(w3.y, h1, fb1.z));
    z1 = fmaf(w3.z, h0, fmaf(w3.w, h1, fb1.w));
    h0 = tanhf(z0); h1 = tanhf(z1);
    // collapsed conv + sigmoid
    float zc   = fmaf(ck.x + ck.z, h0, (ck.y + ck.w) * h1);
    float conv = 1.0f / (1.0f + expf(-zc));
    // sampler 2->4 tanh
    float t0 = tanhf(fmaf(W1a.x, h0, fmaf(W1a.y, conv, b1.x)));
    float t1 = tanhf(fmaf(W1a.z, h0, fmaf(W1a.w, conv, b1.y)));
    float t2 = tanhf(fmaf(W1b.x, h0, fmaf(W1b.y, conv, b1.z)));
    float t3 = tanhf(fmaf(W1b.z, h0, fmaf(W1b.w, conv, b1.w)));
    // dl = l1 - l0 ; p0 = 1/(1+exp(dl))
    float dl = fmaf(t3, W2b.w - W2a.w, fmaf(t2, W2b.z - W2a.z,
               fmaf(t1, W2b.y - W2a.y, fmaf(t0, W2b.x - W2a.x, b2.y - b2.x))));
    g_tab2[idx] = 1.0f / (1.0f + expf(dl));
}

// ---------------- kernel 2: layer-1 tanh + smem bilinear ----------------
__global__ __launch_bounds__(256)
void fraud_kernel(const float4* __restrict__ x4,
                  const float4* __restrict__ fraud_W,   // row 0 only
                  const float4* __restrict__ fraud_b,   // first 2 floats only
                  float4* __restrict__ out4,
                  int n4)
{
    extern __shared__ float tab[];      // TPAD floats (37.6 KB)

    // cooperative table stage: 2353 float4 over 256 threads
    {
        const float4* src = reinterpret_cast<const float4*>(g_tab2);
        float4* dst = reinterpret_cast<float4*>(tab);
        for (int i = threadIdx.x; i < TPAD / 4; i += 256)
            dst[i] = src[i];
    }

    const float4 w0  = __ldg(fraud_W);        // layer-1 weights
    const float4 fb0 = __ldg(fraud_b);        // .x,.y = layer-1 biases
    __syncthreads();

    const int nthreads = gridDim.x * blockDim.x;
    for (int t = blockIdx.x * blockDim.x + threadIdx.x; t < n4; t += nthreads) {
        const float4 in = x4[t];
        float4 r;

        #pragma unroll
        for (int s = 0; s < 2; s++) {
            const float x0 = s ? in.z : in.x;
            const float x1 = s ? in.w : in.y;
            // fraud layer 1 (only MUFU work left per sample)
            float h0 = tanh_fast(fmaf(w0.x, x0, fmaf(w0.y, x1, fb0.x)));
            float h1 = tanh_fast(fmaf(w0.z, x0, fmaf(w0.w, x1, fb0.y)));
            // bilinear lookup of G2(h0,h1); u,v in (0,96)
            float u = fmaf(h0, 48.0f, 48.0f);
            float v = fmaf(h1, 48.0f, 48.0f);
            int ix = min(__float2int_rd(u), TN - 2);
            int iy = min(__float2int_rd(v), TN - 2);
            float fx = u - (float)ix;
            float fy = v - (float)iy;
            const float* row0 = tab + iy * TN + ix;
            float v00 = row0[0];
            float v01 = row0[1];
            float v10 = row0[TN];
            float v11 = row0[TN + 1];
            float g0 = fmaf(fx, v01 - v00, v00);
            float g1 = fmaf(fx, v11 - v10, v10);
            float p0 = fmaf(fy, g1 - g0, g0);
            if (s) { r.z = p0; r.w = 1.0f - p0; }
            else   { r.x = p0; r.y = 1.0f - p0; }
        }
        out4[t] = r;
    }
}

extern "C" void kernel_launch(void* const* d_in, const int* in_sizes, int n_in,
                              void* d_out, int out_size)
{
    static bool attr_done = false;
    if (!attr_done) {   // idempotent attribute set (not a stream op)
        cudaFuncSetAttribute(fraud_kernel,
                             cudaFuncAttributeMaxDynamicSharedMemorySize,
                             TPAD * sizeof(float));
        attr_done = true;
    }

    // node 1: build the 97x97 G2 table (accurate math; 9409 points)
    build_table<<<(TN * TN + 255) / 256, 256>>>(
        (const float4*)d_in[1],            // fraud_W
        (const float4*)d_in[2],            // fraud_b
        (const float4*)d_in[15],           // conv_k
        (const float4*)d_in[16],           // s_W1
        (const float4*)d_in[17],           // s_b1
        (const float4*)d_in[18],           // s_W2
        (const float2*)d_in[19]);          // s_b2

    // node 2: main kernel, grid-stride, 4 blocks/SM resident (smem 37.6KB)
    const int n4 = in_sizes[0] / 4;        // 524288 float4 (2 samples each)
    fraud_kernel<<<592, 256, TPAD * sizeof(float)>>>(
        (const float4*)d_in[0],            // x
        (const float4*)d_in[1],            // fraud_W (row 0 used)
        (const float4*)d_in[2],            // fraud_b (first 2 floats used)
        (float4*)d_out,
        n4);
}

// round 14
// speedup vs baseline: 1.4686x; 1.4686x over previous
#include <cuda_runtime.h>

// FraudDetectionHybrid — autoencoder branch is dead code (recon unused).
// R14: consolidation. Falsified across rounds: MUFU count (R9,R11,R13),
// occupancy (R8,R11), tables in gmem/smem (R10,R11,R13), streaming hints
// (R12), multi-node graphs (R4,R10,R11,R13). Kernel time is pinned at
// 7.9-8.9us across 2x compute variation -> compute-independent floor.
// Best measured point: R4's geometry (2 float4/thread, block 256, grid 1024).
// This round: that geometry + single node + __ldg broadcast weights
// (amortized over 4 samples) + proven f32 MUFU math + default-cached I/O.

__device__ __forceinline__ float tanh_fast(float x) {
    float y;
    asm("tanh.approx.f32 %0, %1;" : "=f"(y) : "f"(x));
    return y;
}

__global__ __launch_bounds__(256, 5)
void fraud_kernel(const float4* __restrict__ x4,
                  const float4* __restrict__ fraud_W,   // [4,2,2] = 4 float4
                  const float4* __restrict__ fraud_b,   // [4,2]   = 2 float4
                  const float4* __restrict__ conv_k,    // [2,2]   = 1 float4
                  const float4* __restrict__ s_W1,      // [4,2]   = 2 float4
                  const float4* __restrict__ s_b1,      // [4]     = 1 float4
                  const float4* __restrict__ s_W2,      // [2,4]   = 2 float4
                  const float2* __restrict__ s_b2,      // [2]     = 1 float2
                  float4* __restrict__ out4)
{
    // grid 1024 x block 256; each thread owns 2 float4 (4 samples),
    // strided by 256 within a 512-float4 block tile -> fully coalesced.
    const int base = blockIdx.x * 512 + threadIdx.x;

    // ---- input loads in flight first (DRAM latency overlapped with the
    //      L1-hit weight loads and derived-constant math below) ----
    const float4 in0 = x4[base];
    const float4 in1 = x4[base + 256];

    // ---- broadcast weight loads (uniform addresses, L1-hit after warmup) ----
    const float4 w0  = __ldg(fraud_W + 0);
    const float4 w1  = __ldg(fraud_W + 1);
    const float4 w2  = __ldg(fraud_W + 2);
    const float4 w3  = __ldg(fraud_W + 3);
    const float4 fb0 = __ldg(fraud_b + 0);
    const float4 fb1 = __ldg(fraud_b + 1);
    const float4 ck  = __ldg(conv_k);
    const float4 W1a = __ldg(s_W1 + 0);
    const float4 W1b = __ldg(s_W1 + 1);
    const float4 b1  = __ldg(s_b1);
    const float4 W2a = __ldg(s_W2 + 0);
    const float4 W2b = __ldg(s_W2 + 1);
    const float2 b2  = __ldg(s_b2);

    // fold conv kernel and output layer into derived constants
    const float c0  = ck.x + ck.z;
    const float c1  = ck.y + ck.w;
    const float dW0 = W2b.x - W2a.x;
    const float dW1 = W2b.y - W2a.y;
    const float dW2 = W2b.z - W2a.z;
    const float dW3 = W2b.w - W2a.w;
    const float db  = b2.y - b2.x;

    auto process = [&](float h0, float h1, float& p0, float& p1) {
        // fraud net: 4 stacked 2x2 affine + f32 MUFU tanh
        float z0 = fmaf(w0.x, h0, fmaf(w0.y, h1, fb0.x));
        float z1 = fmaf(w0.z, h0, fmaf(w0.w, h1, fb0.y));
        h0 = tanh_fast(z0); h1 = tanh_fast(z1);
        z0 = fmaf(w1.x, h0, fmaf(w1.y, h1, fb0.z));
        z1 = fmaf(w1.z, h0, fmaf(w1.w, h1, fb0.w));
        h0 = tanh_fast(z0); h1 = tanh_fast(z1);
        z0 = fmaf(w2.x, h0, fmaf(w2.y, h1, fb1.x));
        z1 = fmaf(w2.z, h0, fmaf(w2.w, h1, fb1.y));
        h0 = tanh_fast(z0); h1 = tanh_fast(z1);
        z0 = fmaf(w3.x, h0, fmaf(w3.y, h1, fb1.z));
        z1 = fmaf(w3.z, h0, fmaf(w3.w, h1, fb1.w));
        h0 = tanh_fast(z0); h1 = tanh_fast(z1);
        // collapsed 2x2 conv + sigmoid via tanh
        float zc   = fmaf(c0, h0, c1 * h1);
        float conv = fmaf(tanh_fast(0.5f * zc), 0.5f, 0.5f);
        // sampler: 2 -> 4 (tanh)
        float t0 = tanh_fast(fmaf(W1a.x, h0, fmaf(W1a.y, conv, b1.x)));
        float t1 = tanh_fast(fmaf(W1a.z, h0, fmaf(W1a.w, conv, b1.y)));
        float t2 = tanh_fast(fmaf(W1b.x, h0, fmaf(W1b.y, conv, b1.z)));
        float t3 = tanh_fast(fmaf(W1b.z, h0, fmaf(W1b.w, conv, b1.w)));
        // 2-way softmax == sigmoid of logit difference
        float dl = fmaf(t3, dW3, fmaf(t2, dW2, fmaf(t1, dW1, fmaf(t0, dW0, db))));
        float s  = tanh_fast(0.5f * dl);
        p1 = fmaf(s,  0.5f, 0.5f);
        p0 = fmaf(s, -0.5f, 0.5f);
    };

    float4 r0, r1;
    process(in0.x, in0.y, r0.x, r0.y);
    process(in0.z, in0.w, r0.z, r0.w);
    process(in1.x, in1.y, r1.x, r1.y);
    process(in1.z, in1.w, r1.z, r1.w);

    out4[base]       = r0;
    out4[base + 256] = r1;
}

extern "C" void kernel_launch(void* const* d_in, const int* in_sizes, int n_in,
                              void* d_out, int out_size)
{
    const int block = 256;
    const int grid = in_sizes[0] / 4 / 512;   // 524288 float4 / 512 per block = 1024
    fraud_kernel<<<grid, block>>>(
        (const float4*)d_in[0],         // x
        (const float4*)d_in[1],         // fraud_W
        (const float4*)d_in[2],         // fraud_b
        (const float4*)d_in[15],        // conv_k
        (const float4*)d_in[16],        // s_W1
        (const float4*)d_in[17],        // s_b1
        (const float4*)d_in[18],        // s_W2
        (const float2*)d_in[19],        // s_b2
        (float4*)d_out);
}